// round 12
// baseline (speedup 1.0000x reference)
#include <cuda_runtime.h>
#include <math.h>
#include <stdint.h>

#define NHEADS 16
#define HDIM   128
#define SEQLEN 2048
#define NBATCH 2
#define HID    2048
#define NBH    (NBATCH*NHEADS)   // 32
#define MROWS  (NBATCH*SEQLEN)   // 4096

// Scratch for projected Q/K/V in [b,h,s,d] layout (32 MB each)
__device__ float g_Q[(size_t)NBH*SEQLEN*HDIM];
__device__ float g_K[(size_t)NBH*SEQLEN*HDIM];
__device__ float g_V[(size_t)NBH*SEQLEN*HDIM];
__device__ float2 g_rope[SEQLEN*64];   // (cos, sin) per (s, j)

__device__ __forceinline__ uint32_t f2tf32(float f) {
    uint32_t r;
    asm("cvt.rna.tf32.f32 %0, %1;" : "=r"(r) : "f"(f));
    return r;
}
__device__ __forceinline__ uint32_t s2u(const void* p) {
    return (uint32_t)__cvta_generic_to_shared(p);
}
// ldmatrix x4: four 8x8 b16 tiles == four tf32 8x4-float fragments.
__device__ __forceinline__ void ldsm4(uint32_t* r, uint32_t addr) {
    asm volatile("ldmatrix.sync.aligned.m8n8.x4.shared.b16 {%0,%1,%2,%3}, [%4];"
                 : "=r"(r[0]), "=r"(r[1]), "=r"(r[2]), "=r"(r[3]) : "r"(addr));
}

__device__ __forceinline__ void mma1688(float* d, const uint32_t* a, const uint32_t* b) {
    asm volatile(
        "mma.sync.aligned.m16n8k8.row.col.f32.tf32.tf32.f32 "
        "{%0,%1,%2,%3}, {%4,%5,%6,%7}, {%8,%9}, {%0,%1,%2,%3};"
        : "+f"(d[0]), "+f"(d[1]), "+f"(d[2]), "+f"(d[3])
        : "r"(a[0]), "r"(a[1]), "r"(a[2]), "r"(a[3]), "r"(b[0]), "r"(b[1]));
}

// ===========================================================================
// QKV projection via tf32 mma.sync + ldmatrix fragment loads.
// 128x128 CTA tile, 8 warps (2x4), 64x32/warp, BK=32, double-buffered.
// ===========================================================================
#define GK_PAD    36
#define GK_BUF    (128*GK_PAD)
#define GK_SMEM_DYN (4*GK_BUF*4)

__global__ __launch_bounds__(256) void qkv_mma_kernel(
    const float* __restrict__ X,
    const float* __restrict__ Wq, const float* __restrict__ bq,
    const float* __restrict__ Wk, const float* __restrict__ bk,
    const float* __restrict__ Wv, const float* __restrict__ bv)
{
    extern __shared__ float gsm[];
    float* sA = gsm;
    float* sB = gsm + 2*GK_BUF;

    const float* W; const float* bias; float* dst;
    if (blockIdx.z == 0)      { W = Wq; bias = bq; dst = g_Q; }
    else if (blockIdx.z == 1) { W = Wk; bias = bk; dst = g_K; }
    else                      { W = Wv; bias = bv; dst = g_V; }

    const int tid  = threadIdx.x;
    const int w    = tid >> 5;
    const int lane = tid & 31;
    const int g    = lane >> 2;
    const int cc   = lane & 3;
    const int wm0  = (w >> 2) * 64;
    const int wn0  = (w & 3) * 32;

    const int m0 = blockIdx.y * 128;
    const int n0 = blockIdx.x * 128;

    const int lrow = tid >> 3;
    const int lc4  = tid & 7;

    const float* Ap = X + (size_t)(m0 + lrow) * HID + lc4 * 4;
    const float* Bp = W + (size_t)(n0 + lrow) * HID + lc4 * 4;

    // ldmatrix per-lane base addresses (bytes)
    const uint32_t aB = s2u(sA) +
        (((wm0 + (lane & 7) + ((lane >> 3) & 1) * 8) * GK_PAD) + ((lane >> 4) << 2)) * 4;
    const uint32_t bB = s2u(sB) +
        (((wn0 + (lane & 7) + ((lane >> 4) << 3)) * GK_PAD) + (((lane >> 3) & 1) << 2)) * 4;

    float acc[4][4][4];
    #pragma unroll
    for (int i = 0; i < 4; i++)
        #pragma unroll
        for (int j = 0; j < 4; j++)
            #pragma unroll
            for (int r = 0; r < 4; r++) acc[i][j][r] = 0.f;

    float4 pa[4], pb[4];

    #pragma unroll
    for (int p = 0; p < 4; p++) {
        pa[p] = *(const float4*)(Ap + (size_t)(p*32) * HID);
        pb[p] = *(const float4*)(Bp + (size_t)(p*32) * HID);
    }
    #pragma unroll
    for (int p = 0; p < 4; p++) {
        uint4 ta = make_uint4(f2tf32(pa[p].x), f2tf32(pa[p].y), f2tf32(pa[p].z), f2tf32(pa[p].w));
        uint4 tb = make_uint4(f2tf32(pb[p].x), f2tf32(pb[p].y), f2tf32(pb[p].z), f2tf32(pb[p].w));
        *(uint4*)(sA + (lrow + p*32)*GK_PAD + lc4*4) = ta;
        *(uint4*)(sB + (lrow + p*32)*GK_PAD + lc4*4) = tb;
    }
    __syncthreads();

    for (int c = 0; c < HID/32; c++) {
        const int cur = c & 1;
        const uint32_t bufOff = (uint32_t)(cur * GK_BUF) * 4;

        if (c < HID/32 - 1) {
            const int k0 = (c + 1) * 32;
            #pragma unroll
            for (int p = 0; p < 4; p++) {
                pa[p] = *(const float4*)(Ap + (size_t)(p*32) * HID + k0);
                pb[p] = *(const float4*)(Bp + (size_t)(p*32) * HID + k0);
            }
        }

        #pragma unroll
        for (int ks = 0; ks < 32; ks += 8) {
            uint32_t af[4][4], bf[4][2];
            #pragma unroll
            for (int mt = 0; mt < 4; mt++)
                ldsm4(af[mt], aB + bufOff + (uint32_t)(mt*16*GK_PAD + ks) * 4);
            #pragma unroll
            for (int ntp = 0; ntp < 2; ntp++) {
                uint32_t r[4];
                ldsm4(r, bB + bufOff + (uint32_t)(ntp*16*GK_PAD + ks) * 4);
                bf[2*ntp  ][0] = r[0]; bf[2*ntp  ][1] = r[1];
                bf[2*ntp+1][0] = r[2]; bf[2*ntp+1][1] = r[3];
            }
            #pragma unroll
            for (int mt = 0; mt < 4; mt++)
                #pragma unroll
                for (int nt = 0; nt < 4; nt++)
                    mma1688(acc[mt][nt], af[mt], bf[nt]);
        }

        if (c < HID/32 - 1) {
            float* An = sA + ((c+1) & 1) * GK_BUF;
            float* Bn = sB + ((c+1) & 1) * GK_BUF;
            #pragma unroll
            for (int p = 0; p < 4; p++) {
                uint4 ta = make_uint4(f2tf32(pa[p].x), f2tf32(pa[p].y), f2tf32(pa[p].z), f2tf32(pa[p].w));
                uint4 tb = make_uint4(f2tf32(pb[p].x), f2tf32(pb[p].y), f2tf32(pb[p].z), f2tf32(pb[p].w));
                *(uint4*)(An + (lrow + p*32)*GK_PAD + lc4*4) = ta;
                *(uint4*)(Bn + (lrow + p*32)*GK_PAD + lc4*4) = tb;
            }
        }
        __syncthreads();
    }

    #pragma unroll
    for (int mt = 0; mt < 4; mt++) {
        #pragma unroll
        for (int half = 0; half < 2; half++) {
            const int m = m0 + wm0 + mt*16 + g + half*8;
            const int b = m >> 11;
            const int s = m & (SEQLEN - 1);
            #pragma unroll
            for (int nt = 0; nt < 4; nt++) {
                const int n  = n0 + wn0 + nt*8 + cc*2;
                const int hh = n >> 7;
                const int dd = n & 127;
                float* op = dst + (((size_t)(b*NHEADS + hh))*SEQLEN + s)*HDIM + dd;
                float2 o;
                o.x = acc[mt][nt][half*2 + 0] + bias[n];
                o.y = acc[mt][nt][half*2 + 1] + bias[n + 1];
                *(float2*)op = o;
            }
        }
    }
}

// ---------------------------------------------------------------------------
// RoPE: table + memory-bound apply.
// ---------------------------------------------------------------------------
__global__ __launch_bounds__(256) void rope_table_kernel()
{
    int idx = blockIdx.x * 256 + threadIdx.x;   // < 2048*64
    int j = idx & 63;
    int s = idx >> 6;
    float inv = exp2f(-(float)j * 0.20762050593046112f);
    float ang = (float)s * inv;
    float sn, cs;
    sincosf(ang, &sn, &cs);
    g_rope[idx] = make_float2(cs, sn);
}

__global__ __launch_bounds__(256) void rope_apply_kernel()
{
    int idx = blockIdx.x * 256 + threadIdx.x;   // < 2^23
    int j  = idx & 63;
    int s  = (idx >> 6) & (SEQLEN - 1);
    int t  = idx >> 17;
    float* base = (t < NBH) ? g_Q : g_K;
    int bh = t & (NBH - 1);
    float* p = base + ((size_t)bh * SEQLEN + s) * HDIM;

    float2 cssn = g_rope[s*64 + j];
    float x1 = p[j], x2 = p[j + 64];
    p[j]      = x1 * cssn.x - x2 * cssn.y;
    p[j + 64] = x2 * cssn.x + x1 * cssn.y;
}

// ===========================================================================
// Flash attention via tf32 mma.sync + ldmatrix fragment loads.
// BM=128 queries/CTA (8 warps x 16 rows), BN=64 kv/tile, d=128.
// ===========================================================================
#define AQ_PAD 132
#define AK_PAD 132
#define AV_PAD 68
#define AP_PAD 68
#define AT_QS  (128*AQ_PAD)
#define AT_KS  (64*AK_PAD)
#define AT_VT  (128*AV_PAD)
#define AT_PS  (128*AP_PAD)
#define ATT2_SMEM ((AT_QS + AT_KS + AT_VT + AT_PS) * 4)   // 171008 B

__global__ __launch_bounds__(256, 1) void attn_mma_kernel(float* __restrict__ out)
{
    extern __shared__ float sm[];
    float* Qs = sm;                   // [128][132] tf32
    float* Ks = Qs + AT_QS;           // [64][132]  tf32
    float* Vt = Ks + AT_KS;           // [128][68]  tf32 (V^T: [d][kv])
    float* Ps = Vt + AT_VT;           // [128][68]  tf32

    const int tid  = threadIdx.x;
    const int w    = tid >> 5;
    const int lane = tid & 31;
    const int g    = lane >> 2;       // 0..7
    const int cc   = lane & 3;        // 0..3
    const int wm   = w * 16;          // warp's query-row base in tile

    const int bh = blockIdx.y;
    const int q0 = blockIdx.x * 128;
    const float* Qg = g_Q + ((size_t)bh * SEQLEN + q0) * HDIM;
    const float* Kg = g_K + (size_t)bh * SEQLEN * HDIM;
    const float* Vg = g_V + (size_t)bh * SEQLEN * HDIM;

    // ldmatrix per-lane base addresses (bytes)
    const uint32_t aQ = s2u(Qs) +
        (((wm + (lane & 7) + ((lane >> 3) & 1) * 8) * AQ_PAD) + ((lane >> 4) << 2)) * 4;
    const uint32_t bK = s2u(Ks) +
        ((((lane & 7) + ((lane >> 4) << 3)) * AK_PAD) + (((lane >> 3) & 1) << 2)) * 4;
    const uint32_t aP = s2u(Ps) +
        (((wm + (lane & 7) + ((lane >> 3) & 1) * 8) * AP_PAD) + ((lane >> 4) << 2)) * 4;
    const uint32_t bV = s2u(Vt) +
        ((((lane & 7) + ((lane >> 4) << 3)) * AV_PAD) + (((lane >> 3) & 1) << 2)) * 4;

    // ---- stage Q (tf32) ----
    {
        const int row  = tid >> 1;          // 0..127
        const int half = tid & 1;
        #pragma unroll
        for (int j = 0; j < 16; j++) {
            const int c4 = half * 16 + j;   // 0..31
            float4 v = *(const float4*)(Qg + (size_t)row * HDIM + c4 * 4);
            uint4 t = make_uint4(f2tf32(v.x), f2tf32(v.y), f2tf32(v.z), f2tf32(v.w));
            *(uint4*)(Qs + row * AQ_PAD + c4 * 4) = t;
        }
    }

    float o[16][4];
    #pragma unroll
    for (int i = 0; i < 16; i++)
        #pragma unroll
        for (int r = 0; r < 4; r++) o[i][r] = 0.f;
    float mi0 = -INFINITY, mi1 = -INFINITY, li0 = 0.f, li1 = 0.f;

    const float scale = 0.08838834764831844f;   // 1/sqrt(128)

    const int krow = tid >> 2;        // 0..63
    const int kq4  = tid & 3;

    __syncthreads();

    for (int n0 = 0; n0 < SEQLEN; n0 += 64) {
        // ---- stage K (tf32) and V^T (tf32) ----
        #pragma unroll
        for (int j = 0; j < 8; j++) {
            const int c4 = kq4 * 8 + j;     // 0..31
            float4 v = *(const float4*)(Kg + (size_t)(n0 + krow) * HDIM + c4 * 4);
            uint4 t = make_uint4(f2tf32(v.x), f2tf32(v.y), f2tf32(v.z), f2tf32(v.w));
            *(uint4*)(Ks + krow * AK_PAD + c4 * 4) = t;

            const int kc4 = kq4 + j * 4;    // 0..31
            float4 vv = *(const float4*)(Vg + (size_t)(n0 + krow) * HDIM + kc4 * 4);
            Vt[(kc4*4+0)*AV_PAD + krow] = __uint_as_float(f2tf32(vv.x));
            Vt[(kc4*4+1)*AV_PAD + krow] = __uint_as_float(f2tf32(vv.y));
            Vt[(kc4*4+2)*AV_PAD + krow] = __uint_as_float(f2tf32(vv.z));
            Vt[(kc4*4+3)*AV_PAD + krow] = __uint_as_float(f2tf32(vv.w));
        }
        __syncthreads();

        // ---- S = Q K^T (warp: 16 x 64) ----
        float s[8][4];
        #pragma unroll
        for (int nt = 0; nt < 8; nt++)
            #pragma unroll
            for (int r = 0; r < 4; r++) s[nt][r] = 0.f;

        #pragma unroll
        for (int ks = 0; ks < 16; ks++) {
            uint32_t a[4];
            ldsm4(a, aQ + ks * 32);
            #pragma unroll
            for (int ntp = 0; ntp < 4; ntp++) {
                uint32_t r[4];
                ldsm4(r, bK + (uint32_t)(ntp * 16 * AK_PAD) * 4 + ks * 32);
                mma1688(s[2*ntp],     a, r);
                mma1688(s[2*ntp + 1], a, r + 2);
            }
        }

        // ---- online softmax (rows g and g+8 of warp tile) ----
        float rmax0 = -INFINITY, rmax1 = -INFINITY;
        #pragma unroll
        for (int nt = 0; nt < 8; nt++) {
            rmax0 = fmaxf(rmax0, fmaxf(s[nt][0], s[nt][1]));
            rmax1 = fmaxf(rmax1, fmaxf(s[nt][2], s[nt][3]));
        }
        rmax0 *= scale; rmax1 *= scale;
        rmax0 = fmaxf(rmax0, __shfl_xor_sync(0xffffffffu, rmax0, 1));
        rmax0 = fmaxf(rmax0, __shfl_xor_sync(0xffffffffu, rmax0, 2));
        rmax1 = fmaxf(rmax1, __shfl_xor_sync(0xffffffffu, rmax1, 1));
        rmax1 = fmaxf(rmax1, __shfl_xor_sync(0xffffffffu, rmax1, 2));

        const float nm0 = fmaxf(mi0, rmax0);
        const float nm1 = fmaxf(mi1, rmax1);
        const float f0 = __expf(mi0 - nm0);
        const float f1 = __expf(mi1 - nm1);
        mi0 = nm0; mi1 = nm1;

        float rs0 = 0.f, rs1 = 0.f;
        #pragma unroll
        for (int nt = 0; nt < 8; nt++) {
            float p0 = __expf(s[nt][0] * scale - nm0);
            float p1 = __expf(s[nt][1] * scale - nm0);
            float p2 = __expf(s[nt][2] * scale - nm1);
            float p3 = __expf(s[nt][3] * scale - nm1);
            rs0 += p0 + p1;
            rs1 += p2 + p3;
            float2 w0, w1;
            w0.x = __uint_as_float(f2tf32(p0));
            w0.y = __uint_as_float(f2tf32(p1));
            w1.x = __uint_as_float(f2tf32(p2));
            w1.y = __uint_as_float(f2tf32(p3));
            *(float2*)(Ps + (wm + g)     * AP_PAD + nt*8 + 2*cc) = w0;
            *(float2*)(Ps + (wm + g + 8) * AP_PAD + nt*8 + 2*cc) = w1;
        }
        rs0 += __shfl_xor_sync(0xffffffffu, rs0, 1);
        rs0 += __shfl_xor_sync(0xffffffffu, rs0, 2);
        rs1 += __shfl_xor_sync(0xffffffffu, rs1, 1);
        rs1 += __shfl_xor_sync(0xffffffffu, rs1, 2);
        li0 = li0 * f0 + rs0;
        li1 = li1 * f1 + rs1;

        #pragma unroll
        for (int nt = 0; nt < 16; nt++) {
            o[nt][0] *= f0; o[nt][1] *= f0;
            o[nt][2] *= f1; o[nt][3] *= f1;
        }
        __syncwarp();

        // ---- O += P V^T (warp: 16 x 128) ----
        #pragma unroll
        for (int ks = 0; ks < 8; ks++) {
            uint32_t a[4];
            ldsm4(a, aP + ks * 32);
            #pragma unroll
            for (int ntp = 0; ntp < 8; ntp++) {
                uint32_t r[4];
                ldsm4(r, bV + (uint32_t)(ntp * 16 * AV_PAD) * 4 + ks * 32);
                mma1688(o[2*ntp],     a, r);
                mma1688(o[2*ntp + 1], a, r + 2);
            }
        }
        __syncthreads();
    }

    // ---- epilogue: out[b, s, hh*128 + d] = o / l ----
    const int b  = bh >> 4;
    const int hh = bh & 15;
    const float inv0 = 1.0f / li0;
    const float inv1 = 1.0f / li1;
    const int m0r = q0 + wm + g;
    #pragma unroll
    for (int nt = 0; nt < 16; nt++) {
        const int dd = nt*8 + 2*cc;
        float* op0 = out + ((size_t)(b * SEQLEN + m0r)) * HID + hh * HDIM + dd;
        float* op1 = out + ((size_t)(b * SEQLEN + m0r + 8)) * HID + hh * HDIM + dd;
        float2 r0, r1;
        r0.x = o[nt][0] * inv0; r0.y = o[nt][1] * inv0;
        r1.x = o[nt][2] * inv1; r1.y = o[nt][3] * inv1;
        *(float2*)op0 = r0;
        *(float2*)op1 = r1;
    }
}

// ---------------------------------------------------------------------------
extern "C" void kernel_launch(void* const* d_in, const int* in_sizes, int n_in,
                              void* d_out, int out_size)
{
    const float* X  = (const float*)d_in[0];
    const float* Wq = (const float*)d_in[1];
    const float* bq = (const float*)d_in[2];
    const float* Wk = (const float*)d_in[3];
    const float* bk = (const float*)d_in[4];
    const float* Wv = (const float*)d_in[5];
    const float* bv = (const float*)d_in[6];
    float* out = (float*)d_out;

    (void)cudaFuncSetAttribute(qkv_mma_kernel,
                               cudaFuncAttributeMaxDynamicSharedMemorySize,
                               GK_SMEM_DYN);
    (void)cudaFuncSetAttribute(attn_mma_kernel,
                               cudaFuncAttributeMaxDynamicSharedMemorySize,
                               ATT2_SMEM);

    dim3 gemm_grid(HID/128, MROWS/128, 3);              // 16 x 32 x 3
    qkv_mma_kernel<<<gemm_grid, 256, GK_SMEM_DYN>>>(X, Wq, bq, Wk, bk, Wv, bv);

    rope_table_kernel<<<(SEQLEN*64)/256, 256>>>();
    rope_apply_kernel<<<(2*NBH*SEQLEN*64)/256, 256>>>();

    dim3 attn_grid(SEQLEN/128, NBH);                    // 16 x 32
    attn_mma_kernel<<<attn_grid, 256, ATT2_SMEM>>>(out);
}

// round 13
// speedup vs baseline: 1.0616x; 1.0616x over previous
#include <cuda_runtime.h>
#include <math.h>
#include <stdint.h>

#define NHEADS 16
#define HDIM   128
#define SEQLEN 2048
#define NBATCH 2
#define HID    2048
#define NBH    (NBATCH*NHEADS)   // 32
#define MROWS  (NBATCH*SEQLEN)   // 4096

// Scratch for projected Q/K/V in [b,h,s,d] layout (32 MB each)
__device__ float g_Q[(size_t)NBH*SEQLEN*HDIM];
__device__ float g_K[(size_t)NBH*SEQLEN*HDIM];
__device__ float g_V[(size_t)NBH*SEQLEN*HDIM];
__device__ float2 g_rope[SEQLEN*64];   // (cos, sin) per (s, j)

__device__ __forceinline__ uint32_t f2tf32(float f) {
    uint32_t r;
    asm("cvt.rna.tf32.f32 %0, %1;" : "=r"(r) : "f"(f));
    return r;
}
__device__ __forceinline__ uint32_t s2u(const void* p) {
    return (uint32_t)__cvta_generic_to_shared(p);
}
// ldmatrix x4: four 8x8 b16 tiles == four tf32 8x4-float fragments.
__device__ __forceinline__ void ldsm4(uint32_t* r, uint32_t addr) {
    asm volatile("ldmatrix.sync.aligned.m8n8.x4.shared.b16 {%0,%1,%2,%3}, [%4];"
                 : "=r"(r[0]), "=r"(r[1]), "=r"(r[2]), "=r"(r[3]) : "r"(addr));
}

__device__ __forceinline__ void mma1688(float* d, const uint32_t* a, const uint32_t* b) {
    asm volatile(
        "mma.sync.aligned.m16n8k8.row.col.f32.tf32.tf32.f32 "
        "{%0,%1,%2,%3}, {%4,%5,%6,%7}, {%8,%9}, {%0,%1,%2,%3};"
        : "+f"(d[0]), "+f"(d[1]), "+f"(d[2]), "+f"(d[3])
        : "r"(a[0]), "r"(a[1]), "r"(a[2]), "r"(a[3]), "r"(b[0]), "r"(b[1]));
}

// ===========================================================================
// QKV projection via tf32 mma.sync (round-10 measured version: scalar LDS)
// ===========================================================================
#define GK_PAD    36
#define GK_BUF    (128*GK_PAD)
#define GK_SMEM_DYN (4*GK_BUF*4)

__global__ __launch_bounds__(256) void qkv_mma_kernel(
    const float* __restrict__ X,
    const float* __restrict__ Wq, const float* __restrict__ bq,
    const float* __restrict__ Wk, const float* __restrict__ bk,
    const float* __restrict__ Wv, const float* __restrict__ bv)
{
    extern __shared__ float gsm[];
    float* sA = gsm;
    float* sB = gsm + 2*GK_BUF;

    const float* W; const float* bias; float* dst;
    if (blockIdx.z == 0)      { W = Wq; bias = bq; dst = g_Q; }
    else if (blockIdx.z == 1) { W = Wk; bias = bk; dst = g_K; }
    else                      { W = Wv; bias = bv; dst = g_V; }

    const int tid  = threadIdx.x;
    const int w    = tid >> 5;
    const int lane = tid & 31;
    const int g    = lane >> 2;
    const int cc   = lane & 3;
    const int wm0  = (w >> 2) * 64;
    const int wn0  = (w & 3) * 32;

    const int m0 = blockIdx.y * 128;
    const int n0 = blockIdx.x * 128;

    const int lrow = tid >> 3;
    const int lc4  = tid & 7;

    const float* Ap = X + (size_t)(m0 + lrow) * HID + lc4 * 4;
    const float* Bp = W + (size_t)(n0 + lrow) * HID + lc4 * 4;

    float acc[4][4][4];
    #pragma unroll
    for (int i = 0; i < 4; i++)
        #pragma unroll
        for (int j = 0; j < 4; j++)
            #pragma unroll
            for (int r = 0; r < 4; r++) acc[i][j][r] = 0.f;

    float4 pa[4], pb[4];

    #pragma unroll
    for (int p = 0; p < 4; p++) {
        pa[p] = *(const float4*)(Ap + (size_t)(p*32) * HID);
        pb[p] = *(const float4*)(Bp + (size_t)(p*32) * HID);
    }
    #pragma unroll
    for (int p = 0; p < 4; p++) {
        uint4 ta = make_uint4(f2tf32(pa[p].x), f2tf32(pa[p].y), f2tf32(pa[p].z), f2tf32(pa[p].w));
        uint4 tb = make_uint4(f2tf32(pb[p].x), f2tf32(pb[p].y), f2tf32(pb[p].z), f2tf32(pb[p].w));
        *(uint4*)(sA + (lrow + p*32)*GK_PAD + lc4*4) = ta;
        *(uint4*)(sB + (lrow + p*32)*GK_PAD + lc4*4) = tb;
    }
    __syncthreads();

    for (int c = 0; c < HID/32; c++) {
        const int cur = c & 1;

        if (c < HID/32 - 1) {
            const int k0 = (c + 1) * 32;
            #pragma unroll
            for (int p = 0; p < 4; p++) {
                pa[p] = *(const float4*)(Ap + (size_t)(p*32) * HID + k0);
                pb[p] = *(const float4*)(Bp + (size_t)(p*32) * HID + k0);
            }
        }

        const float* A0 = sA + cur * GK_BUF;
        const float* B0 = sB + cur * GK_BUF;
        #pragma unroll
        for (int ks = 0; ks < 32; ks += 8) {
            uint32_t af[4][4], bf[4][2];
            #pragma unroll
            for (int mt = 0; mt < 4; mt++) {
                const float* ap = A0 + (wm0 + mt*16 + g)*GK_PAD + ks + cc;
                af[mt][0] = __float_as_uint(ap[0]);
                af[mt][1] = __float_as_uint(ap[8*GK_PAD]);
                af[mt][2] = __float_as_uint(ap[4]);
                af[mt][3] = __float_as_uint(ap[8*GK_PAD + 4]);
            }
            #pragma unroll
            for (int nt = 0; nt < 4; nt++) {
                const float* bp = B0 + (wn0 + nt*8 + g)*GK_PAD + ks + cc;
                bf[nt][0] = __float_as_uint(bp[0]);
                bf[nt][1] = __float_as_uint(bp[4]);
            }
            #pragma unroll
            for (int mt = 0; mt < 4; mt++)
                #pragma unroll
                for (int nt = 0; nt < 4; nt++)
                    mma1688(acc[mt][nt], af[mt], bf[nt]);
        }

        if (c < HID/32 - 1) {
            float* An = sA + ((c+1) & 1) * GK_BUF;
            float* Bn = sB + ((c+1) & 1) * GK_BUF;
            #pragma unroll
            for (int p = 0; p < 4; p++) {
                uint4 ta = make_uint4(f2tf32(pa[p].x), f2tf32(pa[p].y), f2tf32(pa[p].z), f2tf32(pa[p].w));
                uint4 tb = make_uint4(f2tf32(pb[p].x), f2tf32(pb[p].y), f2tf32(pb[p].z), f2tf32(pb[p].w));
                *(uint4*)(An + (lrow + p*32)*GK_PAD + lc4*4) = ta;
                *(uint4*)(Bn + (lrow + p*32)*GK_PAD + lc4*4) = tb;
            }
        }
        __syncthreads();
    }

    #pragma unroll
    for (int mt = 0; mt < 4; mt++) {
        #pragma unroll
        for (int half = 0; half < 2; half++) {
            const int m = m0 + wm0 + mt*16 + g + half*8;
            const int b = m >> 11;
            const int s = m & (SEQLEN - 1);
            #pragma unroll
            for (int nt = 0; nt < 4; nt++) {
                const int n  = n0 + wn0 + nt*8 + cc*2;
                const int hh = n >> 7;
                const int dd = n & 127;
                float* op = dst + (((size_t)(b*NHEADS + hh))*SEQLEN + s)*HDIM + dd;
                float2 o;
                o.x = acc[mt][nt][half*2 + 0] + bias[n];
                o.y = acc[mt][nt][half*2 + 1] + bias[n + 1];
                *(float2*)op = o;
            }
        }
    }
}

// ---------------------------------------------------------------------------
// RoPE: table + memory-bound apply.
// ---------------------------------------------------------------------------
__global__ __launch_bounds__(256) void rope_table_kernel()
{
    int idx = blockIdx.x * 256 + threadIdx.x;   // < 2048*64
    int j = idx & 63;
    int s = idx >> 6;
    float inv = exp2f(-(float)j * 0.20762050593046112f);
    float ang = (float)s * inv;
    float sn, cs;
    sincosf(ang, &sn, &cs);
    g_rope[idx] = make_float2(cs, sn);
}

__global__ __launch_bounds__(256) void rope_apply_kernel()
{
    int idx = blockIdx.x * 256 + threadIdx.x;   // < 2^23
    int j  = idx & 63;
    int s  = (idx >> 6) & (SEQLEN - 1);
    int t  = idx >> 17;
    float* base = (t < NBH) ? g_Q : g_K;
    int bh = t & (NBH - 1);
    float* p = base + ((size_t)bh * SEQLEN + s) * HDIM;

    float2 cssn = g_rope[s*64 + j];
    float x1 = p[j], x2 = p[j + 64];
    p[j]      = x1 * cssn.x - x2 * cssn.y;
    p[j + 64] = x2 * cssn.x + x1 * cssn.y;
}

// ===========================================================================
// Flash attention: tf32 mma.sync + ldmatrix + register-prefetch K/V pipeline.
// BM=128 queries/CTA (8 warps x 16 rows), BN=64 kv/tile, d=128.
// ===========================================================================
#define AQ_PAD 132
#define AK_PAD 132
#define AV_PAD 68
#define AP_PAD 68
#define AT_QS  (128*AQ_PAD)
#define AT_KS  (64*AK_PAD)
#define AT_VT  (128*AV_PAD)
#define AT_PS  (128*AP_PAD)
#define ATT2_SMEM ((AT_QS + AT_KS + AT_VT + AT_PS) * 4)   // 171008 B

__global__ __launch_bounds__(256, 1) void attn_mma_kernel(float* __restrict__ out)
{
    extern __shared__ float sm[];
    float* Qs = sm;                   // [128][132] tf32
    float* Ks = Qs + AT_QS;           // [64][132]  tf32
    float* Vt = Ks + AT_KS;           // [128][68]  tf32 (V^T: [d][kv])
    float* Ps = Vt + AT_VT;           // [128][68]  tf32

    const int tid  = threadIdx.x;
    const int w    = tid >> 5;
    const int lane = tid & 31;
    const int g    = lane >> 2;       // 0..7
    const int cc   = lane & 3;        // 0..3
    const int wm   = w * 16;          // warp's query-row base in tile

    const int bh = blockIdx.y;
    const int q0 = blockIdx.x * 128;
    const float* Qg = g_Q + ((size_t)bh * SEQLEN + q0) * HDIM;
    const float* Kg = g_K + (size_t)bh * SEQLEN * HDIM;
    const float* Vg = g_V + (size_t)bh * SEQLEN * HDIM;

    // ldmatrix per-lane base addresses (bytes)
    const uint32_t aQ = s2u(Qs) +
        (((wm + (lane & 7) + ((lane >> 3) & 1) * 8) * AQ_PAD) + ((lane >> 4) << 2)) * 4;
    const uint32_t bK = s2u(Ks) +
        ((((lane & 7) + ((lane >> 4) << 3)) * AK_PAD) + (((lane >> 3) & 1) << 2)) * 4;
    const uint32_t aP = s2u(Ps) +
        (((wm + (lane & 7) + ((lane >> 3) & 1) * 8) * AP_PAD) + ((lane >> 4) << 2)) * 4;
    const uint32_t bV = s2u(Vt) +
        ((((lane & 7) + ((lane >> 4) << 3)) * AV_PAD) + (((lane >> 3) & 1) << 2)) * 4;

    const int krow = tid >> 2;        // 0..63
    const int kq4  = tid & 3;

    // ---- stage Q (tf32) ----
    {
        const int row  = tid >> 1;          // 0..127
        const int half = tid & 1;
        #pragma unroll
        for (int j = 0; j < 16; j++) {
            const int c4 = half * 16 + j;   // 0..31
            float4 v = *(const float4*)(Qg + (size_t)row * HDIM + c4 * 4);
            uint4 t = make_uint4(f2tf32(v.x), f2tf32(v.y), f2tf32(v.z), f2tf32(v.w));
            *(uint4*)(Qs + row * AQ_PAD + c4 * 4) = t;
        }
    }

    // ---- prefetch tile 0 K/V into registers ----
    float4 pk[8], pv[8];
    #pragma unroll
    for (int j = 0; j < 8; j++) {
        pk[j] = *(const float4*)(Kg + (size_t)krow * HDIM + (kq4*8 + j) * 4);
        pv[j] = *(const float4*)(Vg + (size_t)krow * HDIM + (kq4 + j*4) * 4);
    }

    float o[16][4];
    #pragma unroll
    for (int i = 0; i < 16; i++)
        #pragma unroll
        for (int r = 0; r < 4; r++) o[i][r] = 0.f;
    float mi0 = -INFINITY, mi1 = -INFINITY, li0 = 0.f, li1 = 0.f;

    const float scale = 0.08838834764831844f;   // 1/sqrt(128)

    __syncthreads();

    for (int n0 = 0; n0 < SEQLEN; n0 += 64) {
        // ---- STS K and V^T from prefetched registers (tf32 at store) ----
        #pragma unroll
        for (int j = 0; j < 8; j++) {
            const int c4 = kq4 * 8 + j;     // 0..31
            uint4 t = make_uint4(f2tf32(pk[j].x), f2tf32(pk[j].y),
                                 f2tf32(pk[j].z), f2tf32(pk[j].w));
            *(uint4*)(Ks + krow * AK_PAD + c4 * 4) = t;

            const int kc4 = kq4 + j * 4;    // 0..31
            Vt[(kc4*4+0)*AV_PAD + krow] = __uint_as_float(f2tf32(pv[j].x));
            Vt[(kc4*4+1)*AV_PAD + krow] = __uint_as_float(f2tf32(pv[j].y));
            Vt[(kc4*4+2)*AV_PAD + krow] = __uint_as_float(f2tf32(pv[j].z));
            Vt[(kc4*4+3)*AV_PAD + krow] = __uint_as_float(f2tf32(pv[j].w));
        }
        __syncthreads();

        // ---- issue global prefetch for next tile (overlaps compute) ----
        if (n0 + 64 < SEQLEN) {
            const size_t rbase = (size_t)(n0 + 64 + krow) * HDIM;
            #pragma unroll
            for (int j = 0; j < 8; j++) {
                pk[j] = *(const float4*)(Kg + rbase + (kq4*8 + j) * 4);
                pv[j] = *(const float4*)(Vg + rbase + (kq4 + j*4) * 4);
            }
        }

        // ---- S = Q K^T (warp: 16 x 64) ----
        float s[8][4];
        #pragma unroll
        for (int nt = 0; nt < 8; nt++)
            #pragma unroll
            for (int r = 0; r < 4; r++) s[nt][r] = 0.f;

        #pragma unroll
        for (int ks = 0; ks < 16; ks++) {
            uint32_t a[4];
            ldsm4(a, aQ + ks * 32);
            #pragma unroll
            for (int ntp = 0; ntp < 4; ntp++) {
                uint32_t r[4];
                ldsm4(r, bK + (uint32_t)(ntp * 16 * AK_PAD) * 4 + ks * 32);
                mma1688(s[2*ntp],     a, r);
                mma1688(s[2*ntp + 1], a, r + 2);
            }
        }

        // ---- online softmax (rows g and g+8 of warp tile) ----
        float rmax0 = -INFINITY, rmax1 = -INFINITY;
        #pragma unroll
        for (int nt = 0; nt < 8; nt++) {
            rmax0 = fmaxf(rmax0, fmaxf(s[nt][0], s[nt][1]));
            rmax1 = fmaxf(rmax1, fmaxf(s[nt][2], s[nt][3]));
        }
        rmax0 *= scale; rmax1 *= scale;
        rmax0 = fmaxf(rmax0, __shfl_xor_sync(0xffffffffu, rmax0, 1));
        rmax0 = fmaxf(rmax0, __shfl_xor_sync(0xffffffffu, rmax0, 2));
        rmax1 = fmaxf(rmax1, __shfl_xor_sync(0xffffffffu, rmax1, 1));
        rmax1 = fmaxf(rmax1, __shfl_xor_sync(0xffffffffu, rmax1, 2));

        const float nm0 = fmaxf(mi0, rmax0);
        const float nm1 = fmaxf(mi1, rmax1);
        const float f0 = __expf(mi0 - nm0);
        const float f1 = __expf(mi1 - nm1);
        mi0 = nm0; mi1 = nm1;

        float rs0 = 0.f, rs1 = 0.f;
        #pragma unroll
        for (int nt = 0; nt < 8; nt++) {
            float p0 = __expf(s[nt][0] * scale - nm0);
            float p1 = __expf(s[nt][1] * scale - nm0);
            float p2 = __expf(s[nt][2] * scale - nm1);
            float p3 = __expf(s[nt][3] * scale - nm1);
            rs0 += p0 + p1;
            rs1 += p2 + p3;
            float2 w0, w1;
            w0.x = __uint_as_float(f2tf32(p0));
            w0.y = __uint_as_float(f2tf32(p1));
            w1.x = __uint_as_float(f2tf32(p2));
            w1.y = __uint_as_float(f2tf32(p3));
            *(float2*)(Ps + (wm + g)     * AP_PAD + nt*8 + 2*cc) = w0;
            *(float2*)(Ps + (wm + g + 8) * AP_PAD + nt*8 + 2*cc) = w1;
        }
        rs0 += __shfl_xor_sync(0xffffffffu, rs0, 1);
        rs0 += __shfl_xor_sync(0xffffffffu, rs0, 2);
        rs1 += __shfl_xor_sync(0xffffffffu, rs1, 1);
        rs1 += __shfl_xor_sync(0xffffffffu, rs1, 2);
        li0 = li0 * f0 + rs0;
        li1 = li1 * f1 + rs1;

        #pragma unroll
        for (int nt = 0; nt < 16; nt++) {
            o[nt][0] *= f0; o[nt][1] *= f0;
            o[nt][2] *= f1; o[nt][3] *= f1;
        }
        __syncwarp();

        // ---- O += P V^T (warp: 16 x 128) ----
        #pragma unroll
        for (int ks = 0; ks < 8; ks++) {
            uint32_t a[4];
            ldsm4(a, aP + ks * 32);
            #pragma unroll
            for (int ntp = 0; ntp < 8; ntp++) {
                uint32_t r[4];
                ldsm4(r, bV + (uint32_t)(ntp * 16 * AV_PAD) * 4 + ks * 32);
                mma1688(o[2*ntp],     a, r);
                mma1688(o[2*ntp + 1], a, r + 2);
            }
        }
        __syncthreads();
    }

    // ---- epilogue: out[b, s, hh*128 + d] = o / l ----
    const int b  = bh >> 4;
    const int hh = bh & 15;
    const float inv0 = 1.0f / li0;
    const float inv1 = 1.0f / li1;
    const int m0r = q0 + wm + g;
    #pragma unroll
    for (int nt = 0; nt < 16; nt++) {
        const int dd = nt*8 + 2*cc;
        float* op0 = out + ((size_t)(b * SEQLEN + m0r)) * HID + hh * HDIM + dd;
        float* op1 = out + ((size_t)(b * SEQLEN + m0r + 8)) * HID + hh * HDIM + dd;
        float2 r0, r1;
        r0.x = o[nt][0] * inv0; r0.y = o[nt][1] * inv0;
        r1.x = o[nt][2] * inv1; r1.y = o[nt][3] * inv1;
        *(float2*)op0 = r0;
        *(float2*)op1 = r1;
    }
}

// ---------------------------------------------------------------------------
extern "C" void kernel_launch(void* const* d_in, const int* in_sizes, int n_in,
                              void* d_out, int out_size)
{
    const float* X  = (const float*)d_in[0];
    const float* Wq = (const float*)d_in[1];
    const float* bq = (const float*)d_in[2];
    const float* Wk = (const float*)d_in[3];
    const float* bk = (const float*)d_in[4];
    const float* Wv = (const float*)d_in[5];
    const float* bv = (const float*)d_in[6];
    float* out = (float*)d_out;

    (void)cudaFuncSetAttribute(qkv_mma_kernel,
                               cudaFuncAttributeMaxDynamicSharedMemorySize,
                               GK_SMEM_DYN);
    (void)cudaFuncSetAttribute(attn_mma_kernel,
                               cudaFuncAttributeMaxDynamicSharedMemorySize,
                               ATT2_SMEM);

    dim3 gemm_grid(HID/128, MROWS/128, 3);              // 16 x 32 x 3
    qkv_mma_kernel<<<gemm_grid, 256, GK_SMEM_DYN>>>(X, Wq, bq, Wk, bk, Wv, bv);

    rope_table_kernel<<<(SEQLEN*64)/256, 256>>>();
    rope_apply_kernel<<<(2*NBH*SEQLEN*64)/256, 256>>>();

    dim3 attn_grid(SEQLEN/128, NBH);                    // 16 x 32
    attn_mma_kernel<<<attn_grid, 256, ATT2_SMEM>>>(out);
}